// round 5
// baseline (speedup 1.0000x reference)
#include <cuda_runtime.h>
#include <cstdint>

// CRF Viterbi decode: B=128, T=1024, K=128. One CTA (256 threads) per batch.
// Forward: warp w owns j in [16w,16w+16); lane = h*16+jl; each thread reduces
// 64 i's (f32x2 adds, transitions in regs, 8 accumulators), ONE shfl.xor(16)
// combines halves; logit pre-added before shfl (exact). Double-buffered state
// => one __syncthreads per step. Logits cp.async double-buffered. History ->
// 64MB scratch. Backtrack: warp 0 walks, blocks double-buffered via cp.async,
// u32-monotone map + integer REDUX argmax (exact first-index tie-break).

#define BB 128
#define TT 1024
#define KK 128
#define TC_STRIDE 132
#define SH 68                // padded half stride (floats): bank-shift 4
#define NTHREADS 256

__device__ float g_state[(size_t)BB * TT * KK];

struct __align__(16) SmemLayout {
    float transC[KK * TC_STRIDE];   // transC[j*132 + i] = T[i][j]
    float spad[2][2 * SH];          // double-buffered padded state (2 halves)
    float logit[2][16][KK];         // double-buffered logit staging
    float block[2][64 * KK];        // double-buffered backtrack staging
    int   tags[TT];
    int   lasttag;
};

__device__ __forceinline__ unsigned smem_u32(const void* p) {
    return (unsigned)__cvta_generic_to_shared(p);
}
__device__ __forceinline__ void cp_async16(unsigned dst, const void* src) {
    asm volatile("cp.async.cg.shared.global [%0], [%1], 16;" :: "r"(dst), "l"(src));
}
__device__ __forceinline__ unsigned f32_mono_u32(float x) {
    unsigned b = __float_as_uint(x);
    return b ^ (unsigned)(((int)b >> 31) | 0x80000000);
}

__global__ void __launch_bounds__(NTHREADS, 1)
crf_viterbi_kernel(const float* __restrict__ logits,
                   const int*   __restrict__ lens,
                   const float* __restrict__ trans,
                   float*       __restrict__ out)
{
    extern __shared__ char smraw[];
    SmemLayout& s = *reinterpret_cast<SmemLayout*>(smraw);

    const int b    = blockIdx.x;
    const int tid  = threadIdx.x;
    const int w    = tid >> 5;         // 8 warps
    const int lane = tid & 31;
    const int h    = lane >> 4;        // i-half: [64h, 64h+64)
    const int jl   = lane & 15;
    const int j    = w * 16 + jl;      // output column owned by this thread
    const int len  = lens[b];

    // ---- transC staging (vectorized read, strided scalar STS) ----
    for (int idx = tid * 4; idx < KK * KK; idx += NTHREADS * 4) {
        float4 v = *reinterpret_cast<const float4*>(trans + idx);
        int i  = idx >> 7;
        int jj = idx & (KK - 1);
        s.transC[(jj + 0) * TC_STRIDE + i] = v.x;
        s.transC[(jj + 1) * TC_STRIDE + i] = v.y;
        s.transC[(jj + 2) * TC_STRIDE + i] = v.z;
        s.transC[(jj + 3) * TC_STRIDE + i] = v.w;
    }

    // ---- init state = logits[b, 0, :] ----
    if (tid < KK) {
        float v = logits[((size_t)b * TT) * KK + tid];
        s.spad[0][(tid >> 6) * SH + (tid & 63)] = v;
        g_state[((size_t)b * TT) * KK + tid] = v;
    }

    // ---- prologue: stage logit rows 1..16 into buffer 0 ----
    {
        int r0 = 1 + w;        if (r0 > TT - 1) r0 = TT - 1;
        int r1 = 1 + w + 8;    if (r1 > TT - 1) r1 = TT - 1;
        const float* base = logits + (size_t)b * TT * KK + lane * 4;
        cp_async16(smem_u32(&s.logit[0][w][lane * 4]),     base + (size_t)r0 * KK);
        cp_async16(smem_u32(&s.logit[0][w + 8][lane * 4]), base + (size_t)r1 * KK);
        asm volatile("cp.async.commit_group;");
    }
    __syncthreads();

    // ---- this thread's 64 transitions (i = 64h..64h+63, col j) from SMEM ----
    unsigned long long t2[32];
    #pragma unroll
    for (int m = 0; m < 32; ++m) {
        float2 tp = *reinterpret_cast<const float2*>(
            &s.transC[j * TC_STRIDE + h * 64 + 2 * m]);
        asm("mov.b64 %0, {%1, %2};" : "=l"(t2[m]) : "f"(tp.x), "f"(tp.y));
    }

    const unsigned sb0 = smem_u32(&s.spad[0][h * SH]);
    const unsigned sb1 = smem_u32(&s.spad[1][h * SH]);
    int pr = 0;

    // ================= forward pass (value-only) =================
    for (int t = 1; t < len; ++t) {
        const int rel = t - 1;
        if ((rel & 15) == 0) {
            int g = rel >> 4;
            int base_row = 1 + (g + 1) * 16;
            int r0 = base_row + w;     if (r0 > TT - 1) r0 = TT - 1;
            int r1 = base_row + w + 8; if (r1 > TT - 1) r1 = TT - 1;
            const float* base = logits + (size_t)b * TT * KK + lane * 4;
            int nb = (g + 1) & 1;
            cp_async16(smem_u32(&s.logit[nb][w][lane * 4]),     base + (size_t)r0 * KK);
            cp_async16(smem_u32(&s.logit[nb][w + 8][lane * 4]), base + (size_t)r1 * KK);
            asm volatile("cp.async.commit_group;");
            asm volatile("cp.async.wait_group 1;");
            __syncthreads();
        }

        const unsigned sbr = pr ? sb1 : sb0;
        const float lg = s.logit[(rel >> 4) & 1][rel & 15][j];

        // 64 candidates: 16x LDS.128, 32x add.rn.f32x2, 8-acc fmax tree
        float a0, a1, a2, a3, a4, a5, a6, a7;
        #pragma unroll
        for (int u = 0; u < 16; ++u) {
            unsigned long long p0, p1, c0, c1;
            asm volatile("ld.shared.v2.u64 {%0, %1}, [%2];"
                         : "=l"(p0), "=l"(p1) : "r"(sbr + 16 * u));
            asm("add.rn.f32x2 %0, %1, %2;" : "=l"(c0) : "l"(p0), "l"(t2[2 * u]));
            asm("add.rn.f32x2 %0, %1, %2;" : "=l"(c1) : "l"(p1), "l"(t2[2 * u + 1]));
            float x0, x1, x2, x3;
            asm("mov.b64 {%0, %1}, %2;" : "=f"(x0), "=f"(x1) : "l"(c0));
            asm("mov.b64 {%0, %1}, %2;" : "=f"(x2), "=f"(x3) : "l"(c1));
            if (u == 0)      { a0 = x0; a1 = x1; a2 = x2; a3 = x3; }
            else if (u == 1) { a4 = x0; a5 = x1; a6 = x2; a7 = x3; }
            else if (u & 1)  { a4 = fmaxf(a4, x0); a5 = fmaxf(a5, x1);
                               a6 = fmaxf(a6, x2); a7 = fmaxf(a7, x3); }
            else             { a0 = fmaxf(a0, x0); a1 = fmaxf(a1, x1);
                               a2 = fmaxf(a2, x2); a3 = fmaxf(a3, x3); }
        }
        float b0 = fmaxf(a0, a4), b1 = fmaxf(a1, a5);
        float b2 = fmaxf(a2, a6), b3 = fmaxf(a3, a7);
        float best = fmaxf(fmaxf(b0, b1), fmaxf(b2, b3)) + lg;  // pre-add (exact)
        best = fmaxf(best, __shfl_xor_sync(0xffffffffu, best, 16));

        if (h == 0) {
            s.spad[pr ^ 1][(j >> 6) * SH + (j & 63)] = best;
            g_state[((size_t)b * TT + t) * KK + j] = best;
        }
        pr ^= 1;
        __syncthreads();
    }
    asm volatile("cp.async.wait_all;");

    // ---- last tag = argmax_j final state (first-index tie-break) ----
    if (tid == 0) {
        float bv = s.spad[pr][0];
        int bi = 0;
        for (int i = 1; i < KK; ++i) {
            float v = s.spad[pr][(i >> 6) * SH + (i & 63)];
            if (v > bv) { bv = v; bi = i; }
        }
        s.lasttag = bi;
    }
    __syncthreads();
    const int lt = s.lasttag;

    // tail fill: tags[t] = last_tag for t >= len-1
    for (int t = len - 1 + tid; t < TT; t += NTHREADS) s.tags[t] = lt;

    // ================= backtrack (double-buffered staging + warp-0 walk) =====
    int cur = lt;
    int hi = len - 2;
    int bb2 = 0;
    if (hi >= 0) {
        // stage first block
        {
            int lo2 = hi - 63; if (lo2 < 0) lo2 = 0;
            int n = (hi - lo2 + 1) * KK;
            const float* src = g_state + ((size_t)b * TT + lo2) * KK;
            for (int idx = tid * 4; idx < n; idx += NTHREADS * 4)
                cp_async16(smem_u32(&s.block[0][idx]), src + idx);
            asm volatile("cp.async.commit_group;");
        }
        while (hi >= 0) {
            int lo = hi - 63; if (lo < 0) lo = 0;
            int nhi = lo - 1;
            if (nhi >= 0) {
                int lo2 = nhi - 63; if (lo2 < 0) lo2 = 0;
                int n = (nhi - lo2 + 1) * KK;
                const float* src = g_state + ((size_t)b * TT + lo2) * KK;
                for (int idx = tid * 4; idx < n; idx += NTHREADS * 4)
                    cp_async16(smem_u32(&s.block[bb2 ^ 1][idx]), src + idx);
                asm volatile("cp.async.commit_group;");
                asm volatile("cp.async.wait_group 1;");
            } else {
                asm volatile("cp.async.wait_group 0;");
            }
            __syncthreads();

            if (tid < 32) {
                const float* blk = s.block[bb2];
                float4 sv = *reinterpret_cast<const float4*>(
                    &blk[(hi - lo) * KK + 4 * lane]);
                for (int t = hi; t >= lo; --t) {
                    float4 tv = *reinterpret_cast<const float4*>(
                        &s.transC[cur * TC_STRIDE + 4 * lane]);
                    float4 svn;
                    if (t > lo)
                        svn = *reinterpret_cast<const float4*>(
                            &blk[(t - 1 - lo) * KK + 4 * lane]);
                    unsigned u0 = f32_mono_u32(sv.x + tv.x);
                    unsigned u1 = f32_mono_u32(sv.y + tv.y);
                    unsigned u2 = f32_mono_u32(sv.z + tv.z);
                    unsigned u3 = f32_mono_u32(sv.w + tv.w);
                    unsigned lm = u0; int li = 4 * lane;
                    if (u1 > lm) { lm = u1; li = 4 * lane + 1; }
                    if (u2 > lm) { lm = u2; li = 4 * lane + 2; }
                    if (u3 > lm) { lm = u3; li = 4 * lane + 3; }
                    unsigned gm = __reduce_max_sync(0xffffffffu, lm);
                    unsigned cand = (lm == gm) ? (unsigned)li : 0xffffffffu;
                    cur = (int)__reduce_min_sync(0xffffffffu, cand);
                    if (lane == 0) s.tags[t] = cur;
                    sv = svn;
                }
            }
            __syncthreads();
            hi = nhi;
            bb2 ^= 1;
        }
    }
    __syncthreads();  // covers len==1 path (tags tail-fill -> output)

    // ================= one-hot output =================
    float* ob = out + (size_t)b * TT * KK;
    for (int it = 0; it < TT / 8; ++it) {
        int t = it * 8 + w;
        int tg = s.tags[t];
        float4 v;
        v.x = (tg == 4 * lane + 0) ? 1.0f : 0.0f;
        v.y = (tg == 4 * lane + 1) ? 1.0f : 0.0f;
        v.z = (tg == 4 * lane + 2) ? 1.0f : 0.0f;
        v.w = (tg == 4 * lane + 3) ? 1.0f : 0.0f;
        *reinterpret_cast<float4*>(ob + (size_t)t * KK + 4 * lane) = v;
    }
}

extern "C" void kernel_launch(void* const* d_in, const int* in_sizes, int n_in,
                              void* d_out, int out_size) {
    const float* logits = (const float*)d_in[0];
    const int*   lens   = (const int*)d_in[1];
    const float* trans  = (const float*)d_in[2];
    float*       out    = (float*)d_out;

    cudaFuncSetAttribute(crf_viterbi_kernel,
                         cudaFuncAttributeMaxDynamicSharedMemorySize,
                         (int)sizeof(SmemLayout));
    crf_viterbi_kernel<<<BB, NTHREADS, sizeof(SmemLayout)>>>(logits, lens, trans, out);
}

// round 6
// speedup vs baseline: 1.0453x; 1.0453x over previous
#include <cuda_runtime.h>
#include <cstdint>

// CRF Viterbi decode: B=128, T=1024, K=128. One CTA (128 threads) per batch.
// Forward: thread per output column j; each thread reduces ALL 128 i's
// (broadcast LDS.128 of state, f32x2 adds, transitions in 64 u64 regs,
// 8 accumulators) -> NO cross-thread reduction, no shfl. Double-buffered
// state => one __syncthreads per step. Logits cp.async double-buffered.
// History -> 64MB scratch. Backtrack: warp 0 walks with double-buffered
// cp.async block staging; branchless IMNMX local argmax + integer REDUX
// (exact first-index tie-break matching jnp.argmax). One-hot f32 out.

#define BB 128
#define TT 1024
#define KK 128
#define TC_STRIDE 132
#define NTHREADS 128

__device__ float g_state[(size_t)BB * TT * KK];

struct __align__(16) SmemLayout {
    float transC[KK * TC_STRIDE];   // transC[j*132 + i] = T[i][j]
    float spad[2][KK];              // double-buffered state
    float logit[2][16][KK];         // double-buffered logit staging
    float block[2][64 * KK];        // double-buffered backtrack staging
    int   tags[TT];
    int   lasttag;
};

__device__ __forceinline__ unsigned smem_u32(const void* p) {
    return (unsigned)__cvta_generic_to_shared(p);
}
__device__ __forceinline__ void cp_async16(unsigned dst, const void* src) {
    asm volatile("cp.async.cg.shared.global [%0], [%1], 16;" :: "r"(dst), "l"(src));
}
__device__ __forceinline__ unsigned f32_mono_u32(float x) {
    unsigned b = __float_as_uint(x);
    return b ^ (unsigned)(((int)b >> 31) | 0x80000000);
}

__global__ void __launch_bounds__(NTHREADS, 1)
crf_viterbi_kernel(const float* __restrict__ logits,
                   const int*   __restrict__ lens,
                   const float* __restrict__ trans,
                   float*       __restrict__ out)
{
    extern __shared__ char smraw[];
    SmemLayout& s = *reinterpret_cast<SmemLayout*>(smraw);

    const int b    = blockIdx.x;
    const int tid  = threadIdx.x;
    const int w    = tid >> 5;         // 4 warps
    const int lane = tid & 31;
    const int j    = tid;              // output column owned by this thread
    const int len  = lens[b];

    // ---- transC staging (vectorized read, strided scalar STS; init-only) ----
    for (int idx = tid * 4; idx < KK * KK; idx += NTHREADS * 4) {
        float4 v = *reinterpret_cast<const float4*>(trans + idx);
        int i  = idx >> 7;
        int jj = idx & (KK - 1);
        s.transC[(jj + 0) * TC_STRIDE + i] = v.x;
        s.transC[(jj + 1) * TC_STRIDE + i] = v.y;
        s.transC[(jj + 2) * TC_STRIDE + i] = v.z;
        s.transC[(jj + 3) * TC_STRIDE + i] = v.w;
    }

    // ---- init state = logits[b, 0, :] ----
    {
        float v = logits[((size_t)b * TT) * KK + tid];
        s.spad[0][tid] = v;
        g_state[((size_t)b * TT) * KK + tid] = v;
    }

    // ---- prologue: stage logit rows 1..16 into buffer 0 ----
    {
        const float* base = logits + (size_t)b * TT * KK + lane * 4;
        #pragma unroll
        for (int k = 0; k < 4; ++k) {
            int ridx = w + 4 * k;          // row-in-epoch 0..15
            int r = 1 + ridx;  if (r > TT - 1) r = TT - 1;
            cp_async16(smem_u32(&s.logit[0][ridx][lane * 4]), base + (size_t)r * KK);
        }
        asm volatile("cp.async.commit_group;");
    }
    __syncthreads();

    // ---- this thread's 128 transitions (column j) from SMEM, 64 f32x2 ----
    unsigned long long t2[64];
    #pragma unroll
    for (int m = 0; m < 64; ++m) {
        float2 tp = *reinterpret_cast<const float2*>(
            &s.transC[j * TC_STRIDE + 2 * m]);
        asm("mov.b64 %0, {%1, %2};" : "=l"(t2[m]) : "f"(tp.x), "f"(tp.y));
    }

    const unsigned sb0 = smem_u32(&s.spad[0][0]);
    const unsigned sb1 = smem_u32(&s.spad[1][0]);
    int pr = 0;

    // ================= forward pass (value-only) =================
    for (int t = 1; t < len; ++t) {
        const int rel = t - 1;
        if ((rel & 15) == 0) {
            int g = rel >> 4;
            int base_row = 1 + (g + 1) * 16;
            int nb = (g + 1) & 1;
            const float* base = logits + (size_t)b * TT * KK + lane * 4;
            #pragma unroll
            for (int k = 0; k < 4; ++k) {
                int ridx = w + 4 * k;
                int r = base_row + ridx;  if (r > TT - 1) r = TT - 1;
                cp_async16(smem_u32(&s.logit[nb][ridx][lane * 4]),
                           base + (size_t)r * KK);
            }
            asm volatile("cp.async.commit_group;");
            asm volatile("cp.async.wait_group 1;");
            __syncthreads();
        }

        const unsigned sbr = pr ? sb1 : sb0;
        const float lg = s.logit[(rel >> 4) & 1][rel & 15][j];

        // 128 candidates: 32x broadcast LDS.128, 64x add.rn.f32x2, 8-acc tree
        float a0, a1, a2, a3, a4, a5, a6, a7;
        #pragma unroll
        for (int u = 0; u < 32; ++u) {
            unsigned long long p0, p1, c0, c1;
            asm volatile("ld.shared.v2.u64 {%0, %1}, [%2];"
                         : "=l"(p0), "=l"(p1) : "r"(sbr + 16 * u));
            asm("add.rn.f32x2 %0, %1, %2;" : "=l"(c0) : "l"(p0), "l"(t2[2 * u]));
            asm("add.rn.f32x2 %0, %1, %2;" : "=l"(c1) : "l"(p1), "l"(t2[2 * u + 1]));
            float x0, x1, x2, x3;
            asm("mov.b64 {%0, %1}, %2;" : "=f"(x0), "=f"(x1) : "l"(c0));
            asm("mov.b64 {%0, %1}, %2;" : "=f"(x2), "=f"(x3) : "l"(c1));
            if (u == 0)      { a0 = x0; a1 = x1; a2 = x2; a3 = x3; }
            else if (u == 1) { a4 = x0; a5 = x1; a6 = x2; a7 = x3; }
            else if (u & 1)  { a4 = fmaxf(a4, x0); a5 = fmaxf(a5, x1);
                               a6 = fmaxf(a6, x2); a7 = fmaxf(a7, x3); }
            else             { a0 = fmaxf(a0, x0); a1 = fmaxf(a1, x1);
                               a2 = fmaxf(a2, x2); a3 = fmaxf(a3, x3); }
        }
        float b0 = fmaxf(a0, a4), b1 = fmaxf(a1, a5);
        float b2 = fmaxf(a2, a6), b3 = fmaxf(a3, a7);
        float best = fmaxf(fmaxf(b0, b1), fmaxf(b2, b3)) + lg;

        s.spad[pr ^ 1][j] = best;
        g_state[((size_t)b * TT + t) * KK + j] = best;
        pr ^= 1;
        __syncthreads();
    }
    asm volatile("cp.async.wait_all;");

    // ---- last tag = argmax_j final state (warp 0, first-index tie-break) ----
    if (w == 0) {
        const float* st = s.spad[pr];
        unsigned u0 = f32_mono_u32(st[4 * lane + 0]);
        unsigned u1 = f32_mono_u32(st[4 * lane + 1]);
        unsigned u2 = f32_mono_u32(st[4 * lane + 2]);
        unsigned u3 = f32_mono_u32(st[4 * lane + 3]);
        unsigned lm = max(max(u0, u1), max(u2, u3));
        unsigned gm = __reduce_max_sync(0xffffffffu, lm);
        unsigned cand = (u0 == gm) ? (unsigned)(4 * lane)
                      : (u1 == gm) ? (unsigned)(4 * lane + 1)
                      : (u2 == gm) ? (unsigned)(4 * lane + 2)
                      : (u3 == gm) ? (unsigned)(4 * lane + 3)
                      : 0xffffffffu;
        unsigned bi = __reduce_min_sync(0xffffffffu, cand);
        if (lane == 0) s.lasttag = (int)bi;
    }
    __syncthreads();
    const int lt = s.lasttag;

    // tail fill: tags[t] = last_tag for t >= len-1
    for (int t = len - 1 + tid; t < TT; t += NTHREADS) s.tags[t] = lt;

    // ================= backtrack (double-buffered staging + warp-0 walk) =====
    int cur = lt;
    int hi = len - 2;
    int bb2 = 0;
    if (hi >= 0) {
        {   // stage first block
            int lo2 = hi - 63; if (lo2 < 0) lo2 = 0;
            int n = (hi - lo2 + 1) * KK;
            const float* src = g_state + ((size_t)b * TT + lo2) * KK;
            for (int idx = tid * 4; idx < n; idx += NTHREADS * 4)
                cp_async16(smem_u32(&s.block[0][idx]), src + idx);
            asm volatile("cp.async.commit_group;");
        }
        while (hi >= 0) {
            int lo = hi - 63; if (lo < 0) lo = 0;
            int nhi = lo - 1;
            if (nhi >= 0) {
                int lo2 = nhi - 63; if (lo2 < 0) lo2 = 0;
                int n = (nhi - lo2 + 1) * KK;
                const float* src = g_state + ((size_t)b * TT + lo2) * KK;
                for (int idx = tid * 4; idx < n; idx += NTHREADS * 4)
                    cp_async16(smem_u32(&s.block[bb2 ^ 1][idx]), src + idx);
                asm volatile("cp.async.commit_group;");
                asm volatile("cp.async.wait_group 1;");
            } else {
                asm volatile("cp.async.wait_group 0;");
            }
            __syncthreads();

            if (tid < 32) {
                const float* blk = s.block[bb2];
                float4 sv = *reinterpret_cast<const float4*>(
                    &blk[(hi - lo) * KK + 4 * lane]);
                for (int t = hi; t >= lo; --t) {
                    float4 tv = *reinterpret_cast<const float4*>(
                        &s.transC[cur * TC_STRIDE + 4 * lane]);
                    float4 svn;
                    if (t > lo)
                        svn = *reinterpret_cast<const float4*>(
                            &blk[(t - 1 - lo) * KK + 4 * lane]);
                    unsigned u0 = f32_mono_u32(sv.x + tv.x);
                    unsigned u1 = f32_mono_u32(sv.y + tv.y);
                    unsigned u2 = f32_mono_u32(sv.z + tv.z);
                    unsigned u3 = f32_mono_u32(sv.w + tv.w);
                    unsigned lm = max(max(u0, u1), max(u2, u3));  // IMNMX tree
                    unsigned gm = __reduce_max_sync(0xffffffffu, lm);
                    unsigned cand = (u0 == gm) ? (unsigned)(4 * lane)
                                  : (u1 == gm) ? (unsigned)(4 * lane + 1)
                                  : (u2 == gm) ? (unsigned)(4 * lane + 2)
                                  : (u3 == gm) ? (unsigned)(4 * lane + 3)
                                  : 0xffffffffu;
                    cur = (int)__reduce_min_sync(0xffffffffu, cand);
                    if (lane == 0) s.tags[t] = cur;
                    sv = svn;
                }
            }
            __syncthreads();
            hi = nhi;
            bb2 ^= 1;
        }
    }
    __syncthreads();  // covers len==1 path (tags tail-fill -> output)

    // ================= one-hot output =================
    float* ob = out + (size_t)b * TT * KK;
    for (int it = 0; it < TT / 4; ++it) {
        int t = it * 4 + w;
        int tg = s.tags[t];
        float4 v;
        v.x = (tg == 4 * lane + 0) ? 1.0f : 0.0f;
        v.y = (tg == 4 * lane + 1) ? 1.0f : 0.0f;
        v.z = (tg == 4 * lane + 2) ? 1.0f : 0.0f;
        v.w = (tg == 4 * lane + 3) ? 1.0f : 0.0f;
        *reinterpret_cast<float4*>(ob + (size_t)t * KK + 4 * lane) = v;
    }
}

extern "C" void kernel_launch(void* const* d_in, const int* in_sizes, int n_in,
                              void* d_out, int out_size) {
    const float* logits = (const float*)d_in[0];
    const int*   lens   = (const int*)d_in[1];
    const float* trans  = (const float*)d_in[2];
    float*       out    = (float*)d_out;

    cudaFuncSetAttribute(crf_viterbi_kernel,
                         cudaFuncAttributeMaxDynamicSharedMemorySize,
                         (int)sizeof(SmemLayout));
    crf_viterbi_kernel<<<BB, NTHREADS, sizeof(SmemLayout)>>>(logits, lens, trans, out);
}